// round 2
// baseline (speedup 1.0000x reference)
#include <cuda_runtime.h>
#include <cuda_bf16.h>

#define NN 100000
#define NE 1600000
#define NB_SCAN 196   // ceil(NN/512)

// ---------------- scratch (static device globals; no allocation) ------------
__device__ int   g_deg_in [NN];
__device__ int   g_deg_out[NN];
__device__ int   g_rowptr [NN + 1];
__device__ int   g_cursor [NN];
__device__ int   g_esrc   [NE];
__device__ float g_sin    [NN];
__device__ float g_sout   [NN];
__device__ float g_bufA   [NN * 128];
__device__ float g_bufB   [NN * 128];
__device__ int   g_bsum   [256];
__device__ int   g_boff   [256];

// ---------------- degree / CSR construction --------------------------------
__global__ void k_zero() {
    int i = blockIdx.x * blockDim.x + threadIdx.x;
    if (i < NN) { g_deg_in[i] = 0; g_deg_out[i] = 0; }
}

__global__ void k_count(const int* __restrict__ src, const int* __restrict__ dst) {
    int e = blockIdx.x * blockDim.x + threadIdx.x;
    if (e < NE) {
        atomicAdd(&g_deg_out[src[e]], 1);
        atomicAdd(&g_deg_in [dst[e]], 1);
    }
}

__global__ void k_scales() {
    int i = blockIdx.x * blockDim.x + threadIdx.x;
    if (i < NN) {
        int dout = g_deg_out[i]; if (dout < 1) dout = 1;
        int din  = g_deg_in [i]; if (din  < 1) din  = 1;
        g_sout[i] = rsqrtf((float)dout);
        g_sin [i] = rsqrtf((float)din);
    }
}

__global__ void k_chunksum() {
    __shared__ int s[512];
    int t = threadIdx.x;
    int i = blockIdx.x * 512 + t;
    s[t] = (i < NN) ? g_deg_in[i] : 0;
    __syncthreads();
    for (int o = 256; o > 0; o >>= 1) {
        if (t < o) s[t] += s[t + o];
        __syncthreads();
    }
    if (t == 0) g_bsum[blockIdx.x] = s[0];
}

__global__ void k_scanblocks() {   // <<<1,256>>>
    __shared__ int s[256];
    int t = threadIdx.x;
    int v = (t < NB_SCAN) ? g_bsum[t] : 0;
    s[t] = v; __syncthreads();
    for (int o = 1; o < 256; o <<= 1) {
        int add = (t >= o) ? s[t - o] : 0;
        __syncthreads();
        s[t] += add;
        __syncthreads();
    }
    g_boff[t] = s[t] - v;
    if (t == 0) g_rowptr[NN] = NE;
}

__global__ void k_scanchunks() {
    __shared__ int s[512];
    int t = threadIdx.x;
    int i = blockIdx.x * 512 + t;
    int v = (i < NN) ? g_deg_in[i] : 0;
    s[t] = v; __syncthreads();
    for (int o = 1; o < 512; o <<= 1) {
        int add = (t >= o) ? s[t - o] : 0;
        __syncthreads();
        s[t] += add;
        __syncthreads();
    }
    int val = s[t] - v + g_boff[blockIdx.x];
    if (i < NN) { g_rowptr[i] = val; g_cursor[i] = val; }
}

__global__ void k_fill(const int* __restrict__ src, const int* __restrict__ dst) {
    int e = blockIdx.x * blockDim.x + threadIdx.x;
    if (e < NE) {
        int p = atomicAdd(&g_cursor[dst[e]], 1);
        g_esrc[p] = src[e];
    }
}

// ---------------- fused (scale-by-deg_out) x GEMM ---------------------------
// Y[r, :NC] = (X[r,:128] * sout[r]) @ W[128, NC]
// 128-col version: blockDim (32,8), 64 rows/block, thread = 8 rows x 4 cols.
__global__ void gemm128_kernel(const float* __restrict__ X,
                               const float* __restrict__ W,
                               float* __restrict__ Y) {
    __shared__ float xs[64][128];
    const int tx = threadIdx.x, ty = threadIdx.y;
    const int row0 = blockIdx.x * 64;
    const int tid = ty * 32 + tx;
    for (int i = tid; i < 64 * 128; i += 256) {
        int r = i >> 7, k = i & 127;
        int gr = row0 + r;
        xs[r][k] = (gr < NN) ? X[gr * 128 + k] * g_sout[gr] : 0.f;
    }
    __syncthreads();
    float4 acc[8];
#pragma unroll
    for (int r = 0; r < 8; r++) acc[r] = make_float4(0.f, 0.f, 0.f, 0.f);
#pragma unroll 4
    for (int k = 0; k < 128; k++) {
        float4 w = *reinterpret_cast<const float4*>(W + k * 128 + tx * 4);
#pragma unroll
        for (int r = 0; r < 8; r++) {
            float xv = xs[ty * 8 + r][k];
            acc[r].x += xv * w.x; acc[r].y += xv * w.y;
            acc[r].z += xv * w.z; acc[r].w += xv * w.w;
        }
    }
#pragma unroll
    for (int r = 0; r < 8; r++) {
        int gr = row0 + ty * 8 + r;
        if (gr < NN)
            *reinterpret_cast<float4*>(Y + gr * 128 + tx * 4) = acc[r];
    }
}

// 40-col version: blockDim (40,8), 64 rows/block, thread = 8 rows x 1 col.
__global__ void gemm40_kernel(const float* __restrict__ X,
                              const float* __restrict__ W,
                              float* __restrict__ Y) {
    __shared__ float xs[64][128];
    const int tx = threadIdx.x, ty = threadIdx.y;
    const int row0 = blockIdx.x * 64;
    const int tid = ty * 40 + tx;
    for (int i = tid; i < 64 * 128; i += 320) {
        int r = i >> 7, k = i & 127;
        int gr = row0 + r;
        xs[r][k] = (gr < NN) ? X[gr * 128 + k] * g_sout[gr] : 0.f;
    }
    __syncthreads();
    float acc[8];
#pragma unroll
    for (int r = 0; r < 8; r++) acc[r] = 0.f;
#pragma unroll 4
    for (int k = 0; k < 128; k++) {
        float w = W[k * 40 + tx];
#pragma unroll
        for (int r = 0; r < 8; r++) acc[r] += xs[ty * 8 + r][k] * w;
    }
#pragma unroll
    for (int r = 0; r < 8; r++) {
        int gr = row0 + ty * 8 + r;
        if (gr < NN) Y[gr * 40 + tx] = acc[r];
    }
}

// ---------------- CSR aggregation (warp per dst node, no atomics) ----------
template <bool RELU>
__global__ void agg128_kernel(const float* __restrict__ hw,
                              const float* __restrict__ bias,
                              float* __restrict__ out) {
    int w = (blockIdx.x * blockDim.x + threadIdx.x) >> 5;
    int lane = threadIdx.x & 31;
    if (w >= NN) return;
    int e0 = g_rowptr[w], e1 = g_rowptr[w + 1];
    float4 acc = make_float4(0.f, 0.f, 0.f, 0.f);
    for (int base = e0; base < e1; base += 32) {
        int cnt = e1 - base; if (cnt > 32) cnt = 32;
        int myi = (lane < cnt) ? g_esrc[base + lane] : 0;
        for (int j = 0; j < cnt; j++) {
            int s = __shfl_sync(0xffffffffu, myi, j);
            const float4 v = *reinterpret_cast<const float4*>(hw + s * 128 + lane * 4);
            acc.x += v.x; acc.y += v.y; acc.z += v.z; acc.w += v.w;
        }
    }
    float sc = g_sin[w];
    float4 bb = *reinterpret_cast<const float4*>(bias + lane * 4);
    float4 r;
    r.x = acc.x * sc + bb.x;
    r.y = acc.y * sc + bb.y;
    r.z = acc.z * sc + bb.z;
    r.w = acc.w * sc + bb.w;
    if (RELU) {
        r.x = fmaxf(r.x, 0.f); r.y = fmaxf(r.y, 0.f);
        r.z = fmaxf(r.z, 0.f); r.w = fmaxf(r.w, 0.f);
    }
    *reinterpret_cast<float4*>(out + w * 128 + lane * 4) = r;
}

__global__ void agg40_kernel(const float* __restrict__ hw,
                             const float* __restrict__ bias,
                             float* __restrict__ out) {
    int w = (blockIdx.x * blockDim.x + threadIdx.x) >> 5;
    int lane = threadIdx.x & 31;
    if (w >= NN) return;
    int e0 = g_rowptr[w], e1 = g_rowptr[w + 1];
    float4 acc = make_float4(0.f, 0.f, 0.f, 0.f);
    for (int base = e0; base < e1; base += 32) {
        int cnt = e1 - base; if (cnt > 32) cnt = 32;
        int myi = (lane < cnt) ? g_esrc[base + lane] : 0;
        for (int j = 0; j < cnt; j++) {
            int s = __shfl_sync(0xffffffffu, myi, j);
            if (lane < 10) {
                const float4 v = *reinterpret_cast<const float4*>(hw + s * 40 + lane * 4);
                acc.x += v.x; acc.y += v.y; acc.z += v.z; acc.w += v.w;
            }
        }
    }
    if (lane < 10) {
        float sc = g_sin[w];
        float4 bb = *reinterpret_cast<const float4*>(bias + lane * 4);
        float4 r;
        r.x = acc.x * sc + bb.x;
        r.y = acc.y * sc + bb.y;
        r.z = acc.z * sc + bb.z;
        r.w = acc.w * sc + bb.w;
        *reinterpret_cast<float4*>(out + w * 40 + lane * 4) = r;
    }
}

// ---------------- launch ----------------------------------------------------
extern "C" void kernel_launch(void* const* d_in, const int* in_sizes, int n_in,
                              void* d_out, int out_size) {
    (void)in_sizes; (void)n_in; (void)out_size;
    const float* feat = (const float*)d_in[0];
    const int*   src  = (const int*)  d_in[1];
    const int*   dst  = (const int*)  d_in[2];
    const float* W0   = (const float*)d_in[3];
    const float* b0   = (const float*)d_in[4];
    const float* W1   = (const float*)d_in[5];
    const float* b1   = (const float*)d_in[6];
    const float* W2   = (const float*)d_in[7];
    const float* b2   = (const float*)d_in[8];
    float* out = (float*)d_out;

    float *bufA = nullptr, *bufB = nullptr;
    cudaGetSymbolAddress((void**)&bufA, g_bufA);
    cudaGetSymbolAddress((void**)&bufB, g_bufB);

    const int TB = 256;
    // CSR construction (per launch; graph-capturable, no allocation)
    k_zero      <<<(NN + TB - 1) / TB, TB>>>();
    k_count     <<<(NE + TB - 1) / TB, TB>>>(src, dst);
    k_scales    <<<(NN + TB - 1) / TB, TB>>>();
    k_chunksum  <<<NB_SCAN, 512>>>();
    k_scanblocks<<<1, 256>>>();
    k_scanchunks<<<NB_SCAN, 512>>>();
    k_fill      <<<(NE + TB - 1) / TB, TB>>>(src, dst);

    const int GEMM_BLKS = (NN + 63) / 64;   // 1563
    const int AGG_BLKS  = (NN * 32 + TB - 1) / TB;  // 12500

    // Layer 0: feat -> bufA (gemm) -> bufB (agg+relu)
    gemm128_kernel<<<GEMM_BLKS, dim3(32, 8)>>>(feat, W0, bufA);
    agg128_kernel<true><<<AGG_BLKS, TB>>>(bufA, b0, bufB);
    // Layer 1
    gemm128_kernel<<<GEMM_BLKS, dim3(32, 8)>>>(bufB, W1, bufA);
    agg128_kernel<true><<<AGG_BLKS, TB>>>(bufA, b1, bufB);
    // Layer 2 (no relu), writes final [N,40] to d_out
    gemm40_kernel<<<GEMM_BLKS, dim3(40, 8)>>>(bufB, W2, bufA);
    agg40_kernel<<<AGG_BLKS, TB>>>(bufA, b2, out);
}

// round 3
// speedup vs baseline: 1.0002x; 1.0002x over previous
#include <cuda_runtime.h>
#include <cuda_bf16.h>

#define NN 100000
#define NE 1600000
#define NB_SCAN 196   // ceil(NN/512)

// ---------------- scratch (static device globals; no allocation) ------------
__device__ int   g_deg_in [NN];
__device__ int   g_deg_out[NN];
__device__ int   g_rowptr [NN + 1];
__device__ int   g_cursor [NN];
__device__ int   g_esrc   [NE];
__device__ float g_sin    [NN];
__device__ float g_sout   [NN];
__device__ float g_bufA   [NN * 128];
__device__ float g_bufB   [NN * 128];
__device__ int   g_bsum   [256];
__device__ int   g_boff   [256];

// ---------------- degree / CSR construction --------------------------------
__global__ void k_zero() {
    int i = blockIdx.x * blockDim.x + threadIdx.x;
    if (i < NN) { g_deg_in[i] = 0; g_deg_out[i] = 0; }
}

__global__ void k_count(const int* __restrict__ src, const int* __restrict__ dst) {
    int e = blockIdx.x * blockDim.x + threadIdx.x;
    if (e < NE) {
        atomicAdd(&g_deg_out[src[e]], 1);
        atomicAdd(&g_deg_in [dst[e]], 1);
    }
}

__global__ void k_scales() {
    int i = blockIdx.x * blockDim.x + threadIdx.x;
    if (i < NN) {
        int dout = g_deg_out[i]; if (dout < 1) dout = 1;
        int din  = g_deg_in [i]; if (din  < 1) din  = 1;
        g_sout[i] = rsqrtf((float)dout);
        g_sin [i] = rsqrtf((float)din);
    }
}

__global__ void k_chunksum() {
    __shared__ int s[512];
    int t = threadIdx.x;
    int i = blockIdx.x * 512 + t;
    s[t] = (i < NN) ? g_deg_in[i] : 0;
    __syncthreads();
    for (int o = 256; o > 0; o >>= 1) {
        if (t < o) s[t] += s[t + o];
        __syncthreads();
    }
    if (t == 0) g_bsum[blockIdx.x] = s[0];
}

__global__ void k_scanblocks() {   // <<<1,256>>>
    __shared__ int s[256];
    int t = threadIdx.x;
    int v = (t < NB_SCAN) ? g_bsum[t] : 0;
    s[t] = v; __syncthreads();
    for (int o = 1; o < 256; o <<= 1) {
        int add = (t >= o) ? s[t - o] : 0;
        __syncthreads();
        s[t] += add;
        __syncthreads();
    }
    g_boff[t] = s[t] - v;
    if (t == 0) g_rowptr[NN] = NE;
}

__global__ void k_scanchunks() {
    __shared__ int s[512];
    int t = threadIdx.x;
    int i = blockIdx.x * 512 + t;
    int v = (i < NN) ? g_deg_in[i] : 0;
    s[t] = v; __syncthreads();
    for (int o = 1; o < 512; o <<= 1) {
        int add = (t >= o) ? s[t - o] : 0;
        __syncthreads();
        s[t] += add;
        __syncthreads();
    }
    int val = s[t] - v + g_boff[blockIdx.x];
    if (i < NN) { g_rowptr[i] = val; g_cursor[i] = val; }
}

__global__ void k_fill(const int* __restrict__ src, const int* __restrict__ dst) {
    int e = blockIdx.x * blockDim.x + threadIdx.x;
    if (e < NE) {
        int p = atomicAdd(&g_cursor[dst[e]], 1);
        g_esrc[p] = src[e];
    }
}

// ---------------- fused (scale-by-deg_out) x GEMM ---------------------------
// Y[r, :NC] = (X[r,:128] * sout[r]) @ W[128, NC]
// 128-col version: blockDim (32,8), 64 rows/block, thread = 8 rows x 4 cols.
__global__ void gemm128_kernel(const float* __restrict__ X,
                               const float* __restrict__ W,
                               float* __restrict__ Y) {
    __shared__ float xs[64][128];
    const int tx = threadIdx.x, ty = threadIdx.y;
    const int row0 = blockIdx.x * 64;
    const int tid = ty * 32 + tx;
    for (int i = tid; i < 64 * 128; i += 256) {
        int r = i >> 7, k = i & 127;
        int gr = row0 + r;
        xs[r][k] = (gr < NN) ? X[gr * 128 + k] * g_sout[gr] : 0.f;
    }
    __syncthreads();
    float4 acc[8];
#pragma unroll
    for (int r = 0; r < 8; r++) acc[r] = make_float4(0.f, 0.f, 0.f, 0.f);
#pragma unroll 4
    for (int k = 0; k < 128; k++) {
        float4 w = *reinterpret_cast<const float4*>(W + k * 128 + tx * 4);
#pragma unroll
        for (int r = 0; r < 8; r++) {
            float xv = xs[ty * 8 + r][k];
            acc[r].x += xv * w.x; acc[r].y += xv * w.y;
            acc[r].z += xv * w.z; acc[r].w += xv * w.w;
        }
    }
#pragma unroll
    for (int r = 0; r < 8; r++) {
        int gr = row0 + ty * 8 + r;
        if (gr < NN)
            *reinterpret_cast<float4*>(Y + gr * 128 + tx * 4) = acc[r];
    }
}

// 40-col version: blockDim (40,8), 64 rows/block, thread = 8 rows x 1 col.
__global__ void gemm40_kernel(const float* __restrict__ X,
                              const float* __restrict__ W,
                              float* __restrict__ Y) {
    __shared__ float xs[64][128];
    const int tx = threadIdx.x, ty = threadIdx.y;
    const int row0 = blockIdx.x * 64;
    const int tid = ty * 40 + tx;
    for (int i = tid; i < 64 * 128; i += 320) {
        int r = i >> 7, k = i & 127;
        int gr = row0 + r;
        xs[r][k] = (gr < NN) ? X[gr * 128 + k] * g_sout[gr] : 0.f;
    }
    __syncthreads();
    float acc[8];
#pragma unroll
    for (int r = 0; r < 8; r++) acc[r] = 0.f;
#pragma unroll 4
    for (int k = 0; k < 128; k++) {
        float w = W[k * 40 + tx];
#pragma unroll
        for (int r = 0; r < 8; r++) acc[r] += xs[ty * 8 + r][k] * w;
    }
#pragma unroll
    for (int r = 0; r < 8; r++) {
        int gr = row0 + ty * 8 + r;
        if (gr < NN) Y[gr * 40 + tx] = acc[r];
    }
}

// ---------------- CSR aggregation (warp per dst node, no atomics) ----------
template <bool RELU>
__global__ void agg128_kernel(const float* __restrict__ hw,
                              const float* __restrict__ bias,
                              float* __restrict__ out) {
    int w = (blockIdx.x * blockDim.x + threadIdx.x) >> 5;
    int lane = threadIdx.x & 31;
    if (w >= NN) return;
    int e0 = g_rowptr[w], e1 = g_rowptr[w + 1];
    float4 acc = make_float4(0.f, 0.f, 0.f, 0.f);
    for (int base = e0; base < e1; base += 32) {
        int cnt = e1 - base; if (cnt > 32) cnt = 32;
        int myi = (lane < cnt) ? g_esrc[base + lane] : 0;
        for (int j = 0; j < cnt; j++) {
            int s = __shfl_sync(0xffffffffu, myi, j);
            const float4 v = *reinterpret_cast<const float4*>(hw + s * 128 + lane * 4);
            acc.x += v.x; acc.y += v.y; acc.z += v.z; acc.w += v.w;
        }
    }
    float sc = g_sin[w];
    float4 bb = *reinterpret_cast<const float4*>(bias + lane * 4);
    float4 r;
    r.x = acc.x * sc + bb.x;
    r.y = acc.y * sc + bb.y;
    r.z = acc.z * sc + bb.z;
    r.w = acc.w * sc + bb.w;
    if (RELU) {
        r.x = fmaxf(r.x, 0.f); r.y = fmaxf(r.y, 0.f);
        r.z = fmaxf(r.z, 0.f); r.w = fmaxf(r.w, 0.f);
    }
    *reinterpret_cast<float4*>(out + w * 128 + lane * 4) = r;
}

__global__ void agg40_kernel(const float* __restrict__ hw,
                             const float* __restrict__ bias,
                             float* __restrict__ out) {
    int w = (blockIdx.x * blockDim.x + threadIdx.x) >> 5;
    int lane = threadIdx.x & 31;
    if (w >= NN) return;
    int e0 = g_rowptr[w], e1 = g_rowptr[w + 1];
    float4 acc = make_float4(0.f, 0.f, 0.f, 0.f);
    for (int base = e0; base < e1; base += 32) {
        int cnt = e1 - base; if (cnt > 32) cnt = 32;
        int myi = (lane < cnt) ? g_esrc[base + lane] : 0;
        for (int j = 0; j < cnt; j++) {
            int s = __shfl_sync(0xffffffffu, myi, j);
            if (lane < 10) {
                const float4 v = *reinterpret_cast<const float4*>(hw + s * 40 + lane * 4);
                acc.x += v.x; acc.y += v.y; acc.z += v.z; acc.w += v.w;
            }
        }
    }
    if (lane < 10) {
        float sc = g_sin[w];
        float4 bb = *reinterpret_cast<const float4*>(bias + lane * 4);
        float4 r;
        r.x = acc.x * sc + bb.x;
        r.y = acc.y * sc + bb.y;
        r.z = acc.z * sc + bb.z;
        r.w = acc.w * sc + bb.w;
        *reinterpret_cast<float4*>(out + w * 40 + lane * 4) = r;
    }
}

// ---------------- launch ----------------------------------------------------
extern "C" void kernel_launch(void* const* d_in, const int* in_sizes, int n_in,
                              void* d_out, int out_size) {
    (void)in_sizes; (void)n_in; (void)out_size;
    const float* feat = (const float*)d_in[0];
    const int*   src  = (const int*)  d_in[1];
    const int*   dst  = (const int*)  d_in[2];
    const float* W0   = (const float*)d_in[3];
    const float* b0   = (const float*)d_in[4];
    const float* W1   = (const float*)d_in[5];
    const float* b1   = (const float*)d_in[6];
    const float* W2   = (const float*)d_in[7];
    const float* b2   = (const float*)d_in[8];
    float* out = (float*)d_out;

    float *bufA = nullptr, *bufB = nullptr;
    cudaGetSymbolAddress((void**)&bufA, g_bufA);
    cudaGetSymbolAddress((void**)&bufB, g_bufB);

    const int TB = 256;
    // CSR construction (per launch; graph-capturable, no allocation)
    k_zero      <<<(NN + TB - 1) / TB, TB>>>();
    k_count     <<<(NE + TB - 1) / TB, TB>>>(src, dst);
    k_scales    <<<(NN + TB - 1) / TB, TB>>>();
    k_chunksum  <<<NB_SCAN, 512>>>();
    k_scanblocks<<<1, 256>>>();
    k_scanchunks<<<NB_SCAN, 512>>>();
    k_fill      <<<(NE + TB - 1) / TB, TB>>>(src, dst);

    const int GEMM_BLKS = (NN + 63) / 64;   // 1563
    const int AGG_BLKS  = (NN * 32 + TB - 1) / TB;  // 12500

    // Layer 0: feat -> bufA (gemm) -> bufB (agg+relu)
    gemm128_kernel<<<GEMM_BLKS, dim3(32, 8)>>>(feat, W0, bufA);
    agg128_kernel<true><<<AGG_BLKS, TB>>>(bufA, b0, bufB);
    // Layer 1
    gemm128_kernel<<<GEMM_BLKS, dim3(32, 8)>>>(bufB, W1, bufA);
    agg128_kernel<true><<<AGG_BLKS, TB>>>(bufA, b1, bufB);
    // Layer 2 (no relu), writes final [N,40] to d_out
    gemm40_kernel<<<GEMM_BLKS, dim3(40, 8)>>>(bufB, W2, bufA);
    agg40_kernel<<<AGG_BLKS, TB>>>(bufA, b2, out);
}

// round 4
// speedup vs baseline: 1.0893x; 1.0891x over previous
#include <cuda_runtime.h>
#include <cuda_bf16.h>

#define NN 100000
#define NE 1600000
#define NB_SCAN 196   // ceil(NN/512)

// ---------------- scratch (static device globals; no allocation) ------------
__device__ int    g_deg_in [NN];
__device__ int    g_deg_out[NN];
__device__ int    g_rowptr [NN + 1];
__device__ int    g_cursor [NN];
__device__ int    g_esrc   [NE];
__device__ float  g_sin    [NN];
__device__ float  g_sout   [NN];
__device__ float  g_bufA   [NN * 128];
__device__ float  g_bufB   [NN * 128];
__device__ int    g_bsum   [256];
__device__ int    g_boff   [256];
// packed weights: wp[p][c] = (W[2p][c], W[2p+1][c])
__device__ float2 g_wp0[64 * 128];
__device__ float2 g_wp1[64 * 128];
__device__ float2 g_wp2[64 * 40];

// ---------------- packed f32x2 FMA ------------------------------------------
__device__ __forceinline__ unsigned long long ffma2(unsigned long long a,
                                                    unsigned long long b,
                                                    unsigned long long c) {
    unsigned long long d;
    asm("fma.rn.f32x2 %0, %1, %2, %3;" : "=l"(d) : "l"(a), "l"(b), "l"(c));
    return d;
}

// ---------------- degree / CSR construction --------------------------------
__global__ void k_zero() {
    int i = blockIdx.x * blockDim.x + threadIdx.x;
    if (i < NN) { g_deg_in[i] = 0; g_deg_out[i] = 0; }
}

__global__ void k_count(const int* __restrict__ src, const int* __restrict__ dst) {
    int e = blockIdx.x * blockDim.x + threadIdx.x;
    if (e < NE) {
        atomicAdd(&g_deg_out[src[e]], 1);
        atomicAdd(&g_deg_in [dst[e]], 1);
    }
}

__global__ void k_scales() {
    int i = blockIdx.x * blockDim.x + threadIdx.x;
    if (i < NN) {
        int dout = g_deg_out[i]; if (dout < 1) dout = 1;
        int din  = g_deg_in [i]; if (din  < 1) din  = 1;
        g_sout[i] = rsqrtf((float)dout);
        g_sin [i] = rsqrtf((float)din);
    }
}

__global__ void k_chunksum() {
    __shared__ int s[512];
    int t = threadIdx.x;
    int i = blockIdx.x * 512 + t;
    s[t] = (i < NN) ? g_deg_in[i] : 0;
    __syncthreads();
    for (int o = 256; o > 0; o >>= 1) {
        if (t < o) s[t] += s[t + o];
        __syncthreads();
    }
    if (t == 0) g_bsum[blockIdx.x] = s[0];
}

__global__ void k_scanblocks() {   // <<<1,256>>>
    __shared__ int s[256];
    int t = threadIdx.x;
    int v = (t < NB_SCAN) ? g_bsum[t] : 0;
    s[t] = v; __syncthreads();
    for (int o = 1; o < 256; o <<= 1) {
        int add = (t >= o) ? s[t - o] : 0;
        __syncthreads();
        s[t] += add;
        __syncthreads();
    }
    g_boff[t] = s[t] - v;
    if (t == 0) g_rowptr[NN] = NE;
}

__global__ void k_scanchunks() {
    __shared__ int s[512];
    int t = threadIdx.x;
    int i = blockIdx.x * 512 + t;
    int v = (i < NN) ? g_deg_in[i] : 0;
    s[t] = v; __syncthreads();
    for (int o = 1; o < 512; o <<= 1) {
        int add = (t >= o) ? s[t - o] : 0;
        __syncthreads();
        s[t] += add;
        __syncthreads();
    }
    int val = s[t] - v + g_boff[blockIdx.x];
    if (i < NN) { g_rowptr[i] = val; g_cursor[i] = val; }
}

__global__ void k_fill(const int* __restrict__ src, const int* __restrict__ dst) {
    int e = blockIdx.x * blockDim.x + threadIdx.x;
    if (e < NE) {
        int p = atomicAdd(&g_cursor[dst[e]], 1);
        g_esrc[p] = src[e];
    }
}

// ---------------- weight packing (k-pair interleave) ------------------------
__global__ void k_pack(const float* __restrict__ W0,
                       const float* __restrict__ W1,
                       const float* __restrict__ W2) {
    int i = blockIdx.x * blockDim.x + threadIdx.x;
    if (i < 64 * 128) {
        int p = i >> 7, c = i & 127;
        g_wp0[i] = make_float2(W0[(2 * p) * 128 + c], W0[(2 * p + 1) * 128 + c]);
        g_wp1[i] = make_float2(W1[(2 * p) * 128 + c], W1[(2 * p + 1) * 128 + c]);
    }
    if (i < 64 * 40) {
        int p = i / 40, c = i % 40;
        g_wp2[i] = make_float2(W2[(2 * p) * 40 + c], W2[(2 * p + 1) * 40 + c]);
    }
}

// ---------------- fused (scale-by-deg_out) x GEMM, f32x2 packed -------------
// Y[r, :128] = (X[r,:128] * sout[r]) @ W.   Even-k partial in lane0, odd-k in
// lane1 of each f32x2 accumulator; one horizontal add at the end.
// Block: 64 rows x 128 cols, 256 threads (32,8); thread = 8 rows x 4 cols.
__global__ void __launch_bounds__(256, 2)
gemm128_kernel(const float* __restrict__ X,
               const float2* __restrict__ Wp,
               float* __restrict__ Y) {
    __shared__ float xs[64][128];
    const int tx = threadIdx.x, ty = threadIdx.y;
    const int row0 = blockIdx.x * 64;
    const int tid = ty * 32 + tx;

    // vectorized load of X tile (+ deg_out scaling)
    for (int i = tid; i < 64 * 32; i += 256) {
        int r = i >> 5, k4 = i & 31;
        int gr = row0 + r;
        float4 v;
        if (gr < NN) {
            v = reinterpret_cast<const float4*>(X + (size_t)gr * 128)[k4];
            float s = g_sout[gr];
            v.x *= s; v.y *= s; v.z *= s; v.w *= s;
        } else {
            v = make_float4(0.f, 0.f, 0.f, 0.f);
        }
        reinterpret_cast<float4*>(&xs[r][0])[k4] = v;
    }
    __syncthreads();

    unsigned long long acc[8][4];
#pragma unroll
    for (int r = 0; r < 8; r++)
#pragma unroll
        for (int c = 0; c < 4; c++) acc[r][c] = 0ull;

    const ulonglong2* wbase = reinterpret_cast<const ulonglong2*>(Wp) + tx * 2;

#pragma unroll 2
    for (int p = 0; p < 64; p++) {
        ulonglong2 w01 = wbase[p * 64];      // cols tx*4, tx*4+1
        ulonglong2 w23 = wbase[p * 64 + 1];  // cols tx*4+2, tx*4+3
#pragma unroll
        for (int r = 0; r < 8; r++) {
            unsigned long long xv =
                *reinterpret_cast<const unsigned long long*>(&xs[ty * 8 + r][2 * p]);
            acc[r][0] = ffma2(xv, w01.x, acc[r][0]);
            acc[r][1] = ffma2(xv, w01.y, acc[r][1]);
            acc[r][2] = ffma2(xv, w23.x, acc[r][2]);
            acc[r][3] = ffma2(xv, w23.y, acc[r][3]);
        }
    }

#pragma unroll
    for (int r = 0; r < 8; r++) {
        int gr = row0 + ty * 8 + r;
        if (gr < NN) {
            float4 o;
            float2 f0 = *reinterpret_cast<float2*>(&acc[r][0]);
            float2 f1 = *reinterpret_cast<float2*>(&acc[r][1]);
            float2 f2 = *reinterpret_cast<float2*>(&acc[r][2]);
            float2 f3 = *reinterpret_cast<float2*>(&acc[r][3]);
            o.x = f0.x + f0.y; o.y = f1.x + f1.y;
            o.z = f2.x + f2.y; o.w = f3.x + f3.y;
            *reinterpret_cast<float4*>(Y + (size_t)gr * 128 + tx * 4) = o;
        }
    }
}

// 40-col version: block 64 rows x 40 cols, threads (40,8); thread = 8 rows x 1 col.
__global__ void gemm40_kernel(const float* __restrict__ X,
                              const float2* __restrict__ Wp,
                              float* __restrict__ Y) {
    __shared__ float xs[64][128];
    const int tx = threadIdx.x, ty = threadIdx.y;
    const int row0 = blockIdx.x * 64;
    const int tid = ty * 40 + tx;

    for (int i = tid; i < 64 * 32; i += 320) {
        int r = i >> 5, k4 = i & 31;
        int gr = row0 + r;
        float4 v;
        if (gr < NN) {
            v = reinterpret_cast<const float4*>(X + (size_t)gr * 128)[k4];
            float s = g_sout[gr];
            v.x *= s; v.y *= s; v.z *= s; v.w *= s;
        } else {
            v = make_float4(0.f, 0.f, 0.f, 0.f);
        }
        reinterpret_cast<float4*>(&xs[r][0])[k4] = v;
    }
    __syncthreads();

    unsigned long long acc[8];
#pragma unroll
    for (int r = 0; r < 8; r++) acc[r] = 0ull;

#pragma unroll 2
    for (int p = 0; p < 64; p++) {
        unsigned long long w =
            *reinterpret_cast<const unsigned long long*>(&Wp[p * 40 + tx]);
#pragma unroll
        for (int r = 0; r < 8; r++) {
            unsigned long long xv =
                *reinterpret_cast<const unsigned long long*>(&xs[ty * 8 + r][2 * p]);
            acc[r] = ffma2(xv, w, acc[r]);
        }
    }

#pragma unroll
    for (int r = 0; r < 8; r++) {
        int gr = row0 + ty * 8 + r;
        if (gr < NN) {
            float2 f = *reinterpret_cast<float2*>(&acc[r]);
            Y[(size_t)gr * 40 + tx] = f.x + f.y;
        }
    }
}

// ---------------- CSR aggregation (warp per dst node, no atomics) ----------
template <bool RELU>
__global__ void agg128_kernel(const float* __restrict__ hw,
                              const float* __restrict__ bias,
                              float* __restrict__ out) {
    int w = (blockIdx.x * blockDim.x + threadIdx.x) >> 5;
    int lane = threadIdx.x & 31;
    if (w >= NN) return;
    int e0 = g_rowptr[w], e1 = g_rowptr[w + 1];
    float4 acc = make_float4(0.f, 0.f, 0.f, 0.f);
    for (int base = e0; base < e1; base += 32) {
        int cnt = e1 - base; if (cnt > 32) cnt = 32;
        int myi = (lane < cnt) ? g_esrc[base + lane] : 0;
        for (int j = 0; j < cnt; j++) {
            int s = __shfl_sync(0xffffffffu, myi, j);
            const float4 v = *reinterpret_cast<const float4*>(hw + (size_t)s * 128 + lane * 4);
            acc.x += v.x; acc.y += v.y; acc.z += v.z; acc.w += v.w;
        }
    }
    float sc = g_sin[w];
    float4 bb = *reinterpret_cast<const float4*>(bias + lane * 4);
    float4 r;
    r.x = acc.x * sc + bb.x;
    r.y = acc.y * sc + bb.y;
    r.z = acc.z * sc + bb.z;
    r.w = acc.w * sc + bb.w;
    if (RELU) {
        r.x = fmaxf(r.x, 0.f); r.y = fmaxf(r.y, 0.f);
        r.z = fmaxf(r.z, 0.f); r.w = fmaxf(r.w, 0.f);
    }
    *reinterpret_cast<float4*>(out + (size_t)w * 128 + lane * 4) = r;
}

__global__ void agg40_kernel(const float* __restrict__ hw,
                             const float* __restrict__ bias,
                             float* __restrict__ out) {
    int w = (blockIdx.x * blockDim.x + threadIdx.x) >> 5;
    int lane = threadIdx.x & 31;
    if (w >= NN) return;
    int e0 = g_rowptr[w], e1 = g_rowptr[w + 1];
    float4 acc = make_float4(0.f, 0.f, 0.f, 0.f);
    for (int base = e0; base < e1; base += 32) {
        int cnt = e1 - base; if (cnt > 32) cnt = 32;
        int myi = (lane < cnt) ? g_esrc[base + lane] : 0;
        for (int j = 0; j < cnt; j++) {
            int s = __shfl_sync(0xffffffffu, myi, j);
            if (lane < 10) {
                const float4 v = *reinterpret_cast<const float4*>(hw + (size_t)s * 40 + lane * 4);
                acc.x += v.x; acc.y += v.y; acc.z += v.z; acc.w += v.w;
            }
        }
    }
    if (lane < 10) {
        float sc = g_sin[w];
        float4 bb = *reinterpret_cast<const float4*>(bias + lane * 4);
        float4 r;
        r.x = acc.x * sc + bb.x;
        r.y = acc.y * sc + bb.y;
        r.z = acc.z * sc + bb.z;
        r.w = acc.w * sc + bb.w;
        *reinterpret_cast<float4*>(out + (size_t)w * 40 + lane * 4) = r;
    }
}

// ---------------- launch ----------------------------------------------------
extern "C" void kernel_launch(void* const* d_in, const int* in_sizes, int n_in,
                              void* d_out, int out_size) {
    (void)in_sizes; (void)n_in; (void)out_size;
    const float* feat = (const float*)d_in[0];
    const int*   src  = (const int*)  d_in[1];
    const int*   dst  = (const int*)  d_in[2];
    const float* W0   = (const float*)d_in[3];
    const float* b0   = (const float*)d_in[4];
    const float* W1   = (const float*)d_in[5];
    const float* b1   = (const float*)d_in[6];
    const float* W2   = (const float*)d_in[7];
    const float* b2   = (const float*)d_in[8];
    float* out = (float*)d_out;

    float *bufA = nullptr, *bufB = nullptr;
    float2 *wp0 = nullptr, *wp1 = nullptr, *wp2 = nullptr;
    cudaGetSymbolAddress((void**)&bufA, g_bufA);
    cudaGetSymbolAddress((void**)&bufB, g_bufB);
    cudaGetSymbolAddress((void**)&wp0, g_wp0);
    cudaGetSymbolAddress((void**)&wp1, g_wp1);
    cudaGetSymbolAddress((void**)&wp2, g_wp2);

    const int TB = 256;
    // Weight packing + CSR construction (per launch; graph-capturable)
    k_pack      <<<(64 * 128 + TB - 1) / TB, TB>>>(W0, W1, W2);
    k_zero      <<<(NN + TB - 1) / TB, TB>>>();
    k_count     <<<(NE + TB - 1) / TB, TB>>>(src, dst);
    k_scales    <<<(NN + TB - 1) / TB, TB>>>();
    k_chunksum  <<<NB_SCAN, 512>>>();
    k_scanblocks<<<1, 256>>>();
    k_scanchunks<<<NB_SCAN, 512>>>();
    k_fill      <<<(NE + TB - 1) / TB, TB>>>(src, dst);

    const int GEMM_BLKS = (NN + 63) / 64;           // 1563
    const int AGG_BLKS  = (NN * 32 + TB - 1) / TB;  // 12500

    // Layer 0: feat -> bufA (gemm) -> bufB (agg+relu)
    gemm128_kernel<<<GEMM_BLKS, dim3(32, 8)>>>(feat, wp0, bufA);
    agg128_kernel<true><<<AGG_BLKS, TB>>>(bufA, b0, bufB);
    // Layer 1
    gemm128_kernel<<<GEMM_BLKS, dim3(32, 8)>>>(bufB, wp1, bufA);
    agg128_kernel<true><<<AGG_BLKS, TB>>>(bufA, b1, bufB);
    // Layer 2 (no relu), writes final [N,40] to d_out
    gemm40_kernel<<<GEMM_BLKS, dim3(40, 8)>>>(bufB, wp2, bufA);
    agg40_kernel<<<AGG_BLKS, TB>>>(bufA, b2, out);
}

// round 5
// speedup vs baseline: 1.1241x; 1.0319x over previous
#include <cuda_runtime.h>
#include <cuda_bf16.h>

#define NN 100000
#define NE 1600000
#define NB_SCAN 196   // ceil(NN/512)

// ---------------- scratch (static device globals; no allocation) ------------
__device__ int    g_deg_in [NN];
__device__ int    g_deg_out[NN];
__device__ int    g_rowptr [NN + 1];
__device__ int    g_cursor [NN];
__device__ int    g_esrc   [NE];
__device__ float  g_sin    [NN];
__device__ float  g_sout   [NN];
__device__ float  g_bufA   [NN * 128];
__device__ float  g_bufB   [NN * 128];
__device__ int    g_bsum   [256];
__device__ int    g_boff   [256];
// packed weights: wp[p][c] = (W[2p][c], W[2p+1][c])
__device__ float2 g_wp0[64 * 128];
__device__ float2 g_wp1[64 * 128];
__device__ float2 g_wp2[64 * 40];

// ---------------- packed f32x2 FMA ------------------------------------------
__device__ __forceinline__ unsigned long long ffma2(unsigned long long a,
                                                    unsigned long long b,
                                                    unsigned long long c) {
    unsigned long long d;
    asm("fma.rn.f32x2 %0, %1, %2, %3;" : "=l"(d) : "l"(a), "l"(b), "l"(c));
    return d;
}

// ---------------- launch 1: weight pack + degree zero -----------------------
__global__ void k_pack_zero(const float* __restrict__ W0,
                            const float* __restrict__ W1,
                            const float* __restrict__ W2) {
    int i = blockIdx.x * blockDim.x + threadIdx.x;
    if (i < NN) { g_deg_in[i] = 0; g_deg_out[i] = 0; }
    if (i < 64 * 128) {
        int p = i >> 7, c = i & 127;
        g_wp0[i] = make_float2(W0[(2 * p) * 128 + c], W0[(2 * p + 1) * 128 + c]);
        g_wp1[i] = make_float2(W1[(2 * p) * 128 + c], W1[(2 * p + 1) * 128 + c]);
    }
    if (i < 64 * 40) {
        int p = i / 40, c = i % 40;
        g_wp2[i] = make_float2(W2[(2 * p) * 40 + c], W2[(2 * p + 1) * 40 + c]);
    }
}

// ---------------- launch 2: degree histogram (4 edges / thread) -------------
__global__ void k_count(const int4* __restrict__ src4, const int4* __restrict__ dst4) {
    int e = blockIdx.x * blockDim.x + threadIdx.x;
    if (e < NE / 4) {
        int4 s = src4[e];
        atomicAdd(&g_deg_out[s.x], 1);
        atomicAdd(&g_deg_out[s.y], 1);
        atomicAdd(&g_deg_out[s.z], 1);
        atomicAdd(&g_deg_out[s.w], 1);
        int4 d = dst4[e];
        atomicAdd(&g_deg_in[d.x], 1);
        atomicAdd(&g_deg_in[d.y], 1);
        atomicAdd(&g_deg_in[d.z], 1);
        atomicAdd(&g_deg_in[d.w], 1);
    }
}

// ---------------- launch 3: scales + per-chunk degree sums ------------------
__global__ void k_scales_chunk() {
    __shared__ int s[512];
    int t = threadIdx.x;
    int i = blockIdx.x * 512 + t;
    int din = 0;
    if (i < NN) {
        int dout = g_deg_out[i]; if (dout < 1) dout = 1;
        din = g_deg_in[i];
        int dinc = (din < 1) ? 1 : din;
        g_sout[i] = rsqrtf((float)dout);
        g_sin [i] = rsqrtf((float)dinc);
    }
    s[t] = din;
    __syncthreads();
    for (int o = 256; o > 0; o >>= 1) {
        if (t < o) s[t] += s[t + o];
        __syncthreads();
    }
    if (t == 0) g_bsum[blockIdx.x] = s[0];
}

// ---------------- scan kernels ----------------------------------------------
__global__ void k_scanblocks() {   // <<<1,256>>>
    __shared__ int s[256];
    int t = threadIdx.x;
    int v = (t < NB_SCAN) ? g_bsum[t] : 0;
    s[t] = v; __syncthreads();
    for (int o = 1; o < 256; o <<= 1) {
        int add = (t >= o) ? s[t - o] : 0;
        __syncthreads();
        s[t] += add;
        __syncthreads();
    }
    g_boff[t] = s[t] - v;
    if (t == 0) g_rowptr[NN] = NE;
}

__global__ void k_scanchunks() {
    __shared__ int s[512];
    int t = threadIdx.x;
    int i = blockIdx.x * 512 + t;
    int v = (i < NN) ? g_deg_in[i] : 0;
    s[t] = v; __syncthreads();
    for (int o = 1; o < 512; o <<= 1) {
        int add = (t >= o) ? s[t - o] : 0;
        __syncthreads();
        s[t] += add;
        __syncthreads();
    }
    int val = s[t] - v + g_boff[blockIdx.x];
    if (i < NN) { g_rowptr[i] = val; g_cursor[i] = val; }
}

__global__ void k_fill(const int4* __restrict__ src4, const int4* __restrict__ dst4) {
    int e = blockIdx.x * blockDim.x + threadIdx.x;
    if (e < NE / 4) {
        int4 s = src4[e];
        int4 d = dst4[e];
        g_esrc[atomicAdd(&g_cursor[d.x], 1)] = s.x;
        g_esrc[atomicAdd(&g_cursor[d.y], 1)] = s.y;
        g_esrc[atomicAdd(&g_cursor[d.z], 1)] = s.z;
        g_esrc[atomicAdd(&g_cursor[d.w], 1)] = s.w;
    }
}

// ---------------- fused (scale-by-deg_out) x GEMM, f32x2 packed -------------
// Y[r, :128] = (X[r,:128] * sout[r]) @ W.   Even-k partial in lane0, odd-k in
// lane1 of each f32x2 accumulator; one horizontal add at the end.
// Block: 64 rows x 128 cols, 256 threads (32,8); thread = 8 rows x 4 cols.
__global__ void __launch_bounds__(256, 2)
gemm128_kernel(const float* __restrict__ X,
               const float2* __restrict__ Wp,
               float* __restrict__ Y) {
    __shared__ float xs[64][128];
    const int tx = threadIdx.x, ty = threadIdx.y;
    const int row0 = blockIdx.x * 64;
    const int tid = ty * 32 + tx;

    // vectorized load of X tile (+ deg_out scaling)
    for (int i = tid; i < 64 * 32; i += 256) {
        int r = i >> 5, k4 = i & 31;
        int gr = row0 + r;
        float4 v;
        if (gr < NN) {
            v = reinterpret_cast<const float4*>(X + (size_t)gr * 128)[k4];
            float s = g_sout[gr];
            v.x *= s; v.y *= s; v.z *= s; v.w *= s;
        } else {
            v = make_float4(0.f, 0.f, 0.f, 0.f);
        }
        reinterpret_cast<float4*>(&xs[r][0])[k4] = v;
    }
    __syncthreads();

    unsigned long long acc[8][4];
#pragma unroll
    for (int r = 0; r < 8; r++)
#pragma unroll
        for (int c = 0; c < 4; c++) acc[r][c] = 0ull;

    const ulonglong2* wbase = reinterpret_cast<const ulonglong2*>(Wp) + tx * 2;

#pragma unroll 4
    for (int p = 0; p < 64; p++) {
        ulonglong2 w01 = wbase[p * 64];      // cols tx*4, tx*4+1
        ulonglong2 w23 = wbase[p * 64 + 1];  // cols tx*4+2, tx*4+3
#pragma unroll
        for (int r = 0; r < 8; r++) {
            unsigned long long xv =
                *reinterpret_cast<const unsigned long long*>(&xs[ty * 8 + r][2 * p]);
            acc[r][0] = ffma2(xv, w01.x, acc[r][0]);
            acc[r][1] = ffma2(xv, w01.y, acc[r][1]);
            acc[r][2] = ffma2(xv, w23.x, acc[r][2]);
            acc[r][3] = ffma2(xv, w23.y, acc[r][3]);
        }
    }

#pragma unroll
    for (int r = 0; r < 8; r++) {
        int gr = row0 + ty * 8 + r;
        if (gr < NN) {
            float4 o;
            float2 f0 = *reinterpret_cast<float2*>(&acc[r][0]);
            float2 f1 = *reinterpret_cast<float2*>(&acc[r][1]);
            float2 f2 = *reinterpret_cast<float2*>(&acc[r][2]);
            float2 f3 = *reinterpret_cast<float2*>(&acc[r][3]);
            o.x = f0.x + f0.y; o.y = f1.x + f1.y;
            o.z = f2.x + f2.y; o.w = f3.x + f3.y;
            *reinterpret_cast<float4*>(Y + (size_t)gr * 128 + tx * 4) = o;
        }
    }
}

// 40-col version: block 64 rows x 40 cols, threads (40,8); thread = 8 rows x 1 col.
__global__ void gemm40_kernel(const float* __restrict__ X,
                              const float2* __restrict__ Wp,
                              float* __restrict__ Y) {
    __shared__ float xs[64][128];
    const int tx = threadIdx.x, ty = threadIdx.y;
    const int row0 = blockIdx.x * 64;
    const int tid = ty * 40 + tx;

    for (int i = tid; i < 64 * 32; i += 320) {
        int r = i >> 5, k4 = i & 31;
        int gr = row0 + r;
        float4 v;
        if (gr < NN) {
            v = reinterpret_cast<const float4*>(X + (size_t)gr * 128)[k4];
            float s = g_sout[gr];
            v.x *= s; v.y *= s; v.z *= s; v.w *= s;
        } else {
            v = make_float4(0.f, 0.f, 0.f, 0.f);
        }
        reinterpret_cast<float4*>(&xs[r][0])[k4] = v;
    }
    __syncthreads();

    unsigned long long acc[8];
#pragma unroll
    for (int r = 0; r < 8; r++) acc[r] = 0ull;

#pragma unroll 4
    for (int p = 0; p < 64; p++) {
        unsigned long long w =
            *reinterpret_cast<const unsigned long long*>(&Wp[p * 40 + tx]);
#pragma unroll
        for (int r = 0; r < 8; r++) {
            unsigned long long xv =
                *reinterpret_cast<const unsigned long long*>(&xs[ty * 8 + r][2 * p]);
            acc[r] = ffma2(xv, w, acc[r]);
        }
    }

#pragma unroll
    for (int r = 0; r < 8; r++) {
        int gr = row0 + ty * 8 + r;
        if (gr < NN) {
            float2 f = *reinterpret_cast<float2*>(&acc[r]);
            Y[(size_t)gr * 40 + tx] = f.x + f.y;
        }
    }
}

// ---------------- CSR aggregation (warp per dst node, no atomics) ----------
template <bool RELU>
__global__ void agg128_kernel(const float* __restrict__ hw,
                              const float* __restrict__ bias,
                              float* __restrict__ out) {
    int w = (blockIdx.x * blockDim.x + threadIdx.x) >> 5;
    int lane = threadIdx.x & 31;
    if (w >= NN) return;
    int e0 = g_rowptr[w], e1 = g_rowptr[w + 1];
    float4 acc = make_float4(0.f, 0.f, 0.f, 0.f);
    for (int base = e0; base < e1; base += 32) {
        int cnt = e1 - base; if (cnt > 32) cnt = 32;
        int myi = (lane < cnt) ? g_esrc[base + lane] : 0;
        for (int j = 0; j < cnt; j++) {
            int s = __shfl_sync(0xffffffffu, myi, j);
            const float4 v = *reinterpret_cast<const float4*>(hw + (size_t)s * 128 + lane * 4);
            acc.x += v.x; acc.y += v.y; acc.z += v.z; acc.w += v.w;
        }
    }
    float sc = g_sin[w];
    float4 bb = *reinterpret_cast<const float4*>(bias + lane * 4);
    float4 r;
    r.x = acc.x * sc + bb.x;
    r.y = acc.y * sc + bb.y;
    r.z = acc.z * sc + bb.z;
    r.w = acc.w * sc + bb.w;
    if (RELU) {
        r.x = fmaxf(r.x, 0.f); r.y = fmaxf(r.y, 0.f);
        r.z = fmaxf(r.z, 0.f); r.w = fmaxf(r.w, 0.f);
    }
    *reinterpret_cast<float4*>(out + (size_t)w * 128 + lane * 4) = r;
}

__global__ void agg40_kernel(const float* __restrict__ hw,
                             const float* __restrict__ bias,
                             float* __restrict__ out) {
    int w = (blockIdx.x * blockDim.x + threadIdx.x) >> 5;
    int lane = threadIdx.x & 31;
    if (w >= NN) return;
    int e0 = g_rowptr[w], e1 = g_rowptr[w + 1];
    float4 acc = make_float4(0.f, 0.f, 0.f, 0.f);
    for (int base = e0; base < e1; base += 32) {
        int cnt = e1 - base; if (cnt > 32) cnt = 32;
        int myi = (lane < cnt) ? g_esrc[base + lane] : 0;
        for (int j = 0; j < cnt; j++) {
            int s = __shfl_sync(0xffffffffu, myi, j);
            if (lane < 10) {
                const float4 v = *reinterpret_cast<const float4*>(hw + (size_t)s * 40 + lane * 4);
                acc.x += v.x; acc.y += v.y; acc.z += v.z; acc.w += v.w;
            }
        }
    }
    if (lane < 10) {
        float sc = g_sin[w];
        float4 bb = *reinterpret_cast<const float4*>(bias + lane * 4);
        float4 r;
        r.x = acc.x * sc + bb.x;
        r.y = acc.y * sc + bb.y;
        r.z = acc.z * sc + bb.z;
        r.w = acc.w * sc + bb.w;
        *reinterpret_cast<float4*>(out + (size_t)w * 40 + lane * 4) = r;
    }
}

// ---------------- launch ----------------------------------------------------
extern "C" void kernel_launch(void* const* d_in, const int* in_sizes, int n_in,
                              void* d_out, int out_size) {
    (void)in_sizes; (void)n_in; (void)out_size;
    const float* feat = (const float*)d_in[0];
    const int*   src  = (const int*)  d_in[1];
    const int*   dst  = (const int*)  d_in[2];
    const float* W0   = (const float*)d_in[3];
    const float* b0   = (const float*)d_in[4];
    const float* W1   = (const float*)d_in[5];
    const float* b1   = (const float*)d_in[6];
    const float* W2   = (const float*)d_in[7];
    const float* b2   = (const float*)d_in[8];
    float* out = (float*)d_out;

    float *bufA = nullptr, *bufB = nullptr;
    float2 *wp0 = nullptr, *wp1 = nullptr, *wp2 = nullptr;
    cudaGetSymbolAddress((void**)&bufA, g_bufA);
    cudaGetSymbolAddress((void**)&bufB, g_bufB);
    cudaGetSymbolAddress((void**)&wp0, g_wp0);
    cudaGetSymbolAddress((void**)&wp1, g_wp1);
    cudaGetSymbolAddress((void**)&wp2, g_wp2);

    const int TB = 256;
    const int GEMM_BLKS = (NN + 63) / 64;           // 1563
    const int AGG_BLKS  = (NN * 32 + TB - 1) / TB;  // 12500
    const int E4_BLKS   = (NE / 4 + TB - 1) / TB;   // 1563

    // (1) pack weights + zero degrees
    k_pack_zero   <<<(NN + TB - 1) / TB, TB>>>(W0, W1, W2);
    // (2) degree histogram
    k_count       <<<E4_BLKS, TB>>>((const int4*)src, (const int4*)dst);
    // (3) norm scales + chunk sums
    k_scales_chunk<<<NB_SCAN, 512>>>();
    // (4) layer-0 GEMM (only needs scales + weights) — profiled launch
    gemm128_kernel<<<GEMM_BLKS, dim3(32, 8)>>>(feat, wp0, bufA);
    // (5-7) finish CSR while gemm output is pending
    k_scanblocks  <<<1, 256>>>();
    k_scanchunks  <<<NB_SCAN, 512>>>();
    k_fill        <<<E4_BLKS, TB>>>((const int4*)src, (const int4*)dst);
    // (8) layer-0 aggregation + relu
    agg128_kernel<true><<<AGG_BLKS, TB>>>(bufA, b0, bufB);
    // (9-10) layer 1
    gemm128_kernel<<<GEMM_BLKS, dim3(32, 8)>>>(bufB, wp1, bufA);
    agg128_kernel<true><<<AGG_BLKS, TB>>>(bufA, b1, bufB);
    // (11-12) layer 2 (no relu) -> d_out
    gemm40_kernel<<<GEMM_BLKS, dim3(40, 8)>>>(bufB, wp2, bufA);
    agg40_kernel  <<<AGG_BLKS, TB>>>(bufA, b2, out);
}

// round 6
// speedup vs baseline: 1.1394x; 1.0136x over previous
#include <cuda_runtime.h>
#include <cuda_bf16.h>

#define NN 100000
#define NE 1600000
#define NB_SCAN 196   // ceil(NN/512)

// ---------------- scratch (static device globals; no allocation) ------------
__device__ int    g_deg_in [NN];
__device__ int    g_deg_out[NN];
__device__ int    g_rowptr [NN + 1];
__device__ int    g_cursor [NN];
__device__ int    g_esrc   [NE];
__device__ float  g_sin    [NN];
__device__ float  g_sout   [NN];
__device__ float  g_bufA   [NN * 128];
__device__ float  g_bufB   [NN * 128];
__device__ int    g_bsum   [256];
__device__ int    g_boff   [256];
// dense packed weights (two planes so warp LDG.128 lanes are contiguous):
//   wA[p*32+t] = (W[2p][4t],   W[2p+1][4t],   W[2p][4t+1], W[2p+1][4t+1])
//   wB[p*32+t] = (W[2p][4t+2], W[2p+1][4t+2], W[2p][4t+3], W[2p+1][4t+3])
__device__ float4 g_wA0[64 * 32];
__device__ float4 g_wB0[64 * 32];
__device__ float4 g_wA1[64 * 32];
__device__ float4 g_wB1[64 * 32];
__device__ float2 g_wp2[64 * 40];   // [p][c] = (W2[2p][c], W2[2p+1][c])

// ---------------- packed f32x2 FMA ------------------------------------------
__device__ __forceinline__ unsigned long long ffma2(unsigned long long a,
                                                    unsigned long long b,
                                                    unsigned long long c) {
    unsigned long long d;
    asm("fma.rn.f32x2 %0, %1, %2, %3;" : "=l"(d) : "l"(a), "l"(b), "l"(c));
    return d;
}

// ---------------- launch 1: weight pack + degree zero -----------------------
__global__ void k_pack_zero(const float* __restrict__ W0,
                            const float* __restrict__ W1,
                            const float* __restrict__ W2) {
    int i = blockIdx.x * blockDim.x + threadIdx.x;
    if (i < NN) { g_deg_in[i] = 0; g_deg_out[i] = 0; }
    if (i < 64 * 32) {
        int p = i >> 5, t = i & 31;
        int c0 = 4 * t;
        const float* r0 = W0 + (2 * p) * 128;
        const float* r1 = W0 + (2 * p + 1) * 128;
        g_wA0[i] = make_float4(r0[c0],     r1[c0],     r0[c0 + 1], r1[c0 + 1]);
        g_wB0[i] = make_float4(r0[c0 + 2], r1[c0 + 2], r0[c0 + 3], r1[c0 + 3]);
        r0 = W1 + (2 * p) * 128;
        r1 = W1 + (2 * p + 1) * 128;
        g_wA1[i] = make_float4(r0[c0],     r1[c0],     r0[c0 + 1], r1[c0 + 1]);
        g_wB1[i] = make_float4(r0[c0 + 2], r1[c0 + 2], r0[c0 + 3], r1[c0 + 3]);
    }
    if (i < 64 * 40) {
        int p = i / 40, c = i % 40;
        g_wp2[i] = make_float2(W2[(2 * p) * 40 + c], W2[(2 * p + 1) * 40 + c]);
    }
}

// ---------------- launch 2: degree histogram (4 edges / thread) -------------
__global__ void k_count(const int4* __restrict__ src4, const int4* __restrict__ dst4) {
    int e = blockIdx.x * blockDim.x + threadIdx.x;
    if (e < NE / 4) {
        int4 s = src4[e];
        atomicAdd(&g_deg_out[s.x], 1);
        atomicAdd(&g_deg_out[s.y], 1);
        atomicAdd(&g_deg_out[s.z], 1);
        atomicAdd(&g_deg_out[s.w], 1);
        int4 d = dst4[e];
        atomicAdd(&g_deg_in[d.x], 1);
        atomicAdd(&g_deg_in[d.y], 1);
        atomicAdd(&g_deg_in[d.z], 1);
        atomicAdd(&g_deg_in[d.w], 1);
    }
}

// ---------------- launch 3: scales + per-chunk degree sums ------------------
__global__ void k_scales_chunk() {
    __shared__ int s[512];
    int t = threadIdx.x;
    int i = blockIdx.x * 512 + t;
    int din = 0;
    if (i < NN) {
        int dout = g_deg_out[i]; if (dout < 1) dout = 1;
        din = g_deg_in[i];
        int dinc = (din < 1) ? 1 : din;
        g_sout[i] = rsqrtf((float)dout);
        g_sin [i] = rsqrtf((float)dinc);
    }
    s[t] = din;
    __syncthreads();
    for (int o = 256; o > 0; o >>= 1) {
        if (t < o) s[t] += s[t + o];
        __syncthreads();
    }
    if (t == 0) g_bsum[blockIdx.x] = s[0];
}

// ---------------- scan kernels ----------------------------------------------
__global__ void k_scanblocks() {   // <<<1,256>>>
    __shared__ int s[256];
    int t = threadIdx.x;
    int v = (t < NB_SCAN) ? g_bsum[t] : 0;
    s[t] = v; __syncthreads();
    for (int o = 1; o < 256; o <<= 1) {
        int add = (t >= o) ? s[t - o] : 0;
        __syncthreads();
        s[t] += add;
        __syncthreads();
    }
    g_boff[t] = s[t] - v;
    if (t == 0) g_rowptr[NN] = NE;
}

__global__ void k_scanchunks() {
    __shared__ int s[512];
    int t = threadIdx.x;
    int i = blockIdx.x * 512 + t;
    int v = (i < NN) ? g_deg_in[i] : 0;
    s[t] = v; __syncthreads();
    for (int o = 1; o < 512; o <<= 1) {
        int add = (t >= o) ? s[t - o] : 0;
        __syncthreads();
        s[t] += add;
        __syncthreads();
    }
    int val = s[t] - v + g_boff[blockIdx.x];
    if (i < NN) { g_rowptr[i] = val; g_cursor[i] = val; }
}

__global__ void k_fill(const int4* __restrict__ src4, const int4* __restrict__ dst4) {
    int e = blockIdx.x * blockDim.x + threadIdx.x;
    if (e < NE / 4) {
        int4 s = src4[e];
        int4 d = dst4[e];
        g_esrc[atomicAdd(&g_cursor[d.x], 1)] = s.x;
        g_esrc[atomicAdd(&g_cursor[d.y], 1)] = s.y;
        g_esrc[atomicAdd(&g_cursor[d.z], 1)] = s.z;
        g_esrc[atomicAdd(&g_cursor[d.w], 1)] = s.w;
    }
}

// ---------------- fused (scale-by-deg_out) x GEMM, f32x2 packed -------------
// Y[r, :128] = (X[r,:128] * sout[r]) @ W.
// Block: 64 rows x 128 cols, 256 threads (32,8); thread = 8 rows x 4 cols.
// Weights in dense two-plane layout -> warp LDG.128 covers contiguous 512B.
// x loaded as 16B broadcast LDS (2 k-pairs per load).
__global__ void __launch_bounds__(256, 2)
gemm128_kernel(const float* __restrict__ X,
               const float4* __restrict__ WA,
               const float4* __restrict__ WB,
               float* __restrict__ Y) {
    __shared__ float xs[64][128];
    const int tx = threadIdx.x, ty = threadIdx.y;
    const int row0 = blockIdx.x * 64;
    const int tid = ty * 32 + tx;

    // vectorized load of X tile (+ deg_out scaling)
    for (int i = tid; i < 64 * 32; i += 256) {
        int r = i >> 5, k4 = i & 31;
        int gr = row0 + r;
        float4 v;
        if (gr < NN) {
            v = reinterpret_cast<const float4*>(X + (size_t)gr * 128)[k4];
            float s = g_sout[gr];
            v.x *= s; v.y *= s; v.z *= s; v.w *= s;
        } else {
            v = make_float4(0.f, 0.f, 0.f, 0.f);
        }
        reinterpret_cast<float4*>(&xs[r][0])[k4] = v;
    }
    __syncthreads();

    unsigned long long acc[8][4];
#pragma unroll
    for (int r = 0; r < 8; r++)
#pragma unroll
        for (int c = 0; c < 4; c++) acc[r][c] = 0ull;

    const ulonglong2* wa = reinterpret_cast<const ulonglong2*>(WA) + tx;
    const ulonglong2* wb = reinterpret_cast<const ulonglong2*>(WB) + tx;

    // q indexes 2 k-pairs (4 k values) at a time
#pragma unroll 2
    for (int q = 0; q < 32; q++) {
        ulonglong2 wa0 = wa[(2 * q) * 32];      // pair 2q,  cols 4tx..4tx+1
        ulonglong2 wb0 = wb[(2 * q) * 32];      // pair 2q,  cols 4tx+2..4tx+3
        ulonglong2 wa1 = wa[(2 * q + 1) * 32];  // pair 2q+1
        ulonglong2 wb1 = wb[(2 * q + 1) * 32];
#pragma unroll
        for (int r = 0; r < 8; r++) {
            ulonglong2 xv =
                *reinterpret_cast<const ulonglong2*>(&xs[ty * 8 + r][4 * q]);
            acc[r][0] = ffma2(xv.x, wa0.x, acc[r][0]);
            acc[r][1] = ffma2(xv.x, wa0.y, acc[r][1]);
            acc[r][2] = ffma2(xv.x, wb0.x, acc[r][2]);
            acc[r][3] = ffma2(xv.x, wb0.y, acc[r][3]);
            acc[r][0] = ffma2(xv.y, wa1.x, acc[r][0]);
            acc[r][1] = ffma2(xv.y, wa1.y, acc[r][1]);
            acc[r][2] = ffma2(xv.y, wb1.x, acc[r][2]);
            acc[r][3] = ffma2(xv.y, wb1.y, acc[r][3]);
        }
    }

#pragma unroll
    for (int r = 0; r < 8; r++) {
        int gr = row0 + ty * 8 + r;
        if (gr < NN) {
            float4 o;
            float2 f0 = *reinterpret_cast<float2*>(&acc[r][0]);
            float2 f1 = *reinterpret_cast<float2*>(&acc[r][1]);
            float2 f2 = *reinterpret_cast<float2*>(&acc[r][2]);
            float2 f3 = *reinterpret_cast<float2*>(&acc[r][3]);
            o.x = f0.x + f0.y; o.y = f1.x + f1.y;
            o.z = f2.x + f2.y; o.w = f3.x + f3.y;
            *reinterpret_cast<float4*>(Y + (size_t)gr * 128 + tx * 4) = o;
        }
    }
}

// 40-col version: block 64 rows x 40 cols, threads (40,8); thread = 8 rows x 1 col.
__global__ void gemm40_kernel(const float* __restrict__ X,
                              const float2* __restrict__ Wp,
                              float* __restrict__ Y) {
    __shared__ float xs[64][128];
    const int tx = threadIdx.x, ty = threadIdx.y;
    const int row0 = blockIdx.x * 64;
    const int tid = ty * 40 + tx;

    for (int i = tid; i < 64 * 32; i += 320) {
        int r = i >> 5, k4 = i & 31;
        int gr = row0 + r;
        float4 v;
        if (gr < NN) {
            v = reinterpret_cast<const float4*>(X + (size_t)gr * 128)[k4];
            float s = g_sout[gr];
            v.x *= s; v.y *= s; v.z *= s; v.w *= s;
        } else {
            v = make_float4(0.f, 0.f, 0.f, 0.f);
        }
        reinterpret_cast<float4*>(&xs[r][0])[k4] = v;
    }
    __syncthreads();

    unsigned long long acc[8];
#pragma unroll
    for (int r = 0; r < 8; r++) acc[r] = 0ull;

#pragma unroll 2
    for (int q = 0; q < 32; q++) {
        unsigned long long w0 =
            *reinterpret_cast<const unsigned long long*>(&Wp[(2 * q) * 40 + tx]);
        unsigned long long w1 =
            *reinterpret_cast<const unsigned long long*>(&Wp[(2 * q + 1) * 40 + tx]);
#pragma unroll
        for (int r = 0; r < 8; r++) {
            ulonglong2 xv =
                *reinterpret_cast<const ulonglong2*>(&xs[ty * 8 + r][4 * q]);
            acc[r] = ffma2(xv.x, w0, acc[r]);
            acc[r] = ffma2(xv.y, w1, acc[r]);
        }
    }

#pragma unroll
    for (int r = 0; r < 8; r++) {
        int gr = row0 + ty * 8 + r;
        if (gr < NN) {
            float2 f = *reinterpret_cast<float2*>(&acc[r]);
            Y[(size_t)gr * 40 + tx] = f.x + f.y;
        }
    }
}

// ---------------- CSR aggregation (warp per dst node, no atomics) ----------
template <bool RELU>
__global__ void agg128_kernel(const float* __restrict__ hw,
                              const float* __restrict__ bias,
                              float* __restrict__ out) {
    int w = (blockIdx.x * blockDim.x + threadIdx.x) >> 5;
    int lane = threadIdx.x & 31;
    if (w >= NN) return;
    int e0 = g_rowptr[w], e1 = g_rowptr[w + 1];
    float4 acc = make_float4(0.f, 0.f, 0.f, 0.f);
    for (int base = e0; base < e1; base += 32) {
        int cnt = e1 - base; if (cnt > 32) cnt = 32;
        int myi = (lane < cnt) ? g_esrc[base + lane] : 0;
        for (int j = 0; j < cnt; j++) {
            int s = __shfl_sync(0xffffffffu, myi, j);
            const float4 v = *reinterpret_cast<const float4*>(hw + (size_t)s * 128 + lane * 4);
            acc.x += v.x; acc.y += v.y; acc.z += v.z; acc.w += v.w;
        }
    }
    float sc = g_sin[w];
    float4 bb = *reinterpret_cast<const float4*>(bias + lane * 4);
    float4 r;
    r.x = acc.x * sc + bb.x;
    r.y = acc.y * sc + bb.y;
    r.z = acc.z * sc + bb.z;
    r.w = acc.w * sc + bb.w;
    if (RELU) {
        r.x = fmaxf(r.x, 0.f); r.y = fmaxf(r.y, 0.f);
        r.z = fmaxf(r.z, 0.f); r.w = fmaxf(r.w, 0.f);
    }
    *reinterpret_cast<float4*>(out + (size_t)w * 128 + lane * 4) = r;
}

__global__ void agg40_kernel(const float* __restrict__ hw,
                             const float* __restrict__ bias,
                             float* __restrict__ out) {
    int w = (blockIdx.x * blockDim.x + threadIdx.x) >> 5;
    int lane = threadIdx.x & 31;
    if (w >= NN) return;
    int e0 = g_rowptr[w], e1 = g_rowptr[w + 1];
    float4 acc = make_float4(0.f, 0.f, 0.f, 0.f);
    for (int base = e0; base < e1; base += 32) {
        int cnt = e1 - base; if (cnt > 32) cnt = 32;
        int myi = (lane < cnt) ? g_esrc[base + lane] : 0;
        for (int j = 0; j < cnt; j++) {
            int s = __shfl_sync(0xffffffffu, myi, j);
            if (lane < 10) {
                const float4 v = *reinterpret_cast<const float4*>(hw + (size_t)s * 40 + lane * 4);
                acc.x += v.x; acc.y += v.y; acc.z += v.z; acc.w += v.w;
            }
        }
    }
    if (lane < 10) {
        float sc = g_sin[w];
        float4 bb = *reinterpret_cast<const float4*>(bias + lane * 4);
        float4 r;
        r.x = acc.x * sc + bb.x;
        r.y = acc.y * sc + bb.y;
        r.z = acc.z * sc + bb.z;
        r.w = acc.w * sc + bb.w;
        *reinterpret_cast<float4*>(out + (size_t)w * 40 + lane * 4) = r;
    }
}

// ---------------- launch ----------------------------------------------------
extern "C" void kernel_launch(void* const* d_in, const int* in_sizes, int n_in,
                              void* d_out, int out_size) {
    (void)in_sizes; (void)n_in; (void)out_size;
    const float* feat = (const float*)d_in[0];
    const int*   src  = (const int*)  d_in[1];
    const int*   dst  = (const int*)  d_in[2];
    const float* W0   = (const float*)d_in[3];
    const float* b0   = (const float*)d_in[4];
    const float* W1   = (const float*)d_in[5];
    const float* b1   = (const float*)d_in[6];
    const float* W2   = (const float*)d_in[7];
    const float* b2   = (const float*)d_in[8];
    float* out = (float*)d_out;

    float *bufA = nullptr, *bufB = nullptr;
    float4 *wA0 = nullptr, *wB0 = nullptr, *wA1 = nullptr, *wB1 = nullptr;
    float2 *wp2 = nullptr;
    cudaGetSymbolAddress((void**)&bufA, g_bufA);
    cudaGetSymbolAddress((void**)&bufB, g_bufB);
    cudaGetSymbolAddress((void**)&wA0, g_wA0);
    cudaGetSymbolAddress((void**)&wB0, g_wB0);
    cudaGetSymbolAddress((void**)&wA1, g_wA1);
    cudaGetSymbolAddress((void**)&wB1, g_wB1);
    cudaGetSymbolAddress((void**)&wp2, g_wp2);

    const int TB = 256;
    const int GEMM_BLKS = (NN + 63) / 64;           // 1563
    const int AGG_BLKS  = (NN * 32 + TB - 1) / TB;  // 12500
    const int E4_BLKS   = (NE / 4 + TB - 1) / TB;   // 1563

    // (1) pack weights + zero degrees
    k_pack_zero   <<<(NN + TB - 1) / TB, TB>>>(W0, W1, W2);
    // (2) degree histogram
    k_count       <<<E4_BLKS, TB>>>((const int4*)src, (const int4*)dst);
    // (3) norm scales + chunk sums
    k_scales_chunk<<<NB_SCAN, 512>>>();
    // (4) layer-0 GEMM (only needs scales + weights) — profiled launch
    gemm128_kernel<<<GEMM_BLKS, dim3(32, 8)>>>(feat, wA0, wB0, bufA);
    // (5-7) finish CSR while gemm output is pending
    k_scanblocks  <<<1, 256>>>();
    k_scanchunks  <<<NB_SCAN, 512>>>();
    k_fill        <<<E4_BLKS, TB>>>((const int4*)src, (const int4*)dst);
    // (8) layer-0 aggregation + relu
    agg128_kernel<true><<<AGG_BLKS, TB>>>(bufA, b0, bufB);
    // (9-10) layer 1
    gemm128_kernel<<<GEMM_BLKS, dim3(32, 8)>>>(bufB, wA1, wB1, bufA);
    agg128_kernel<true><<<AGG_BLKS, TB>>>(bufA, b1, bufB);
    // (11-12) layer 2 (no relu) -> d_out
    gemm40_kernel <<<GEMM_BLKS, dim3(40, 8)>>>(bufB, wp2, bufA);
    agg40_kernel  <<<AGG_BLKS, TB>>>(bufA, b2, out);
}